// round 12
// baseline (speedup 1.0000x reference)
#include <cuda_runtime.h>
#include <cuda_fp16.h>
#include <cstdint>

// Problem: out[524288,128] = x[524288,128] @ W[128,128]^T + b[128]
// Single fp16 GEMM (fp32 accumulate). W fragments in registers.
// R10 structure + dependency-free prefetch.global.L2 burst two tiles ahead.
#define BATCH    524288
#define N_TILES  4096            // BATCH / 128
#define THREADS  256             // 8 warps: 2(M) x 4(N) grid of 64x32 warp tiles

// SMEM: two X stages (fp16 128x128, XOR-swizzled 16B chunks), 32KB each.
#define XSTAGE_BYTES 32768
#define SMEM_BYTES   (65536 + 1024)

__device__ __forceinline__ uint32_t smem_u32(const void* p) {
    uint32_t a;
    asm("{ .reg .u64 t; cvta.to.shared.u64 t, %1; cvt.u32.u64 %0, t; }" : "=r"(a) : "l"(p));
    return a;
}

__device__ __forceinline__ uint32_t pack_f16x2(float a, float b) {
    uint32_t r;
    asm("cvt.rn.f16x2.f32 %0, %1, %2;" : "=r"(r) : "f"(b), "f"(a));  // lo=a, hi=b
    return r;
}

__device__ __forceinline__ void ldsm4(uint32_t addr, uint32_t* r) {
    asm volatile("ldmatrix.sync.aligned.m8n8.x4.shared.b16 {%0,%1,%2,%3}, [%4];"
                 : "=r"(r[0]), "=r"(r[1]), "=r"(r[2]), "=r"(r[3]) : "r"(addr));
}

__device__ __forceinline__ void mma_fp16(float* c, const uint32_t* a, uint32_t b0, uint32_t b1) {
    asm volatile("mma.sync.aligned.m16n8k16.row.col.f32.f16.f16.f32 "
                 "{%0,%1,%2,%3}, {%4,%5,%6,%7}, {%8,%9}, {%0,%1,%2,%3};"
                 : "+f"(c[0]), "+f"(c[1]), "+f"(c[2]), "+f"(c[3])
                 : "r"(a[0]), "r"(a[1]), "r"(a[2]), "r"(a[3]), "r"(b0), "r"(b1));
}

__device__ __forceinline__ void prefetch_l2(const void* p) {
    asm volatile("prefetch.global.L2 [%0];" :: "l"(p));
}

// Store one fp32x4 row chunk (row, k=4l..4l+3) into swizzled fp16 SMEM.
// Element (row,k): row*256 + (((k>>3) ^ (row&7))<<4) + (k&7)*2
__device__ __forceinline__ void convert_row(float4 v, uint32_t dst, int row, int l) {
    uint32_t off = (uint32_t)row * 256u
                 + (((uint32_t)(l >> 1) ^ (uint32_t)(row & 7)) << 4)
                 + (uint32_t)((l & 1) * 8);
    uint32_t p0 = pack_f16x2(v.x, v.y);
    uint32_t p1 = pack_f16x2(v.z, v.w);
    asm volatile("st.shared.v2.b32 [%0], {%1,%2};" :: "r"(dst + off), "r"(p0), "r"(p1) : "memory");
}

__global__ void __launch_bounds__(THREADS, 1)
linear_mma_kernel(const float* __restrict__ x,
                  const float* __restrict__ W,
                  const float* __restrict__ bias,
                  float* __restrict__ out) {
    extern __shared__ char smem_raw[];
    uint32_t base = (smem_u32(smem_raw) + 1023u) & ~1023u;

    const int tid = threadIdx.x;
    const int w   = tid >> 5;        // warp 0..7
    const int l   = tid & 31;

    // Warp tile: 64(M) x 32(N).  2x4 warp grid.
    const int m_off = (w >> 2) * 64;
    const int n_off = (w & 3) * 32;

    // ldmatrix lane mapping (x4 over 16x16 fp16 tiles)
    const int t4 = l >> 3;
    const int r8 = (t4 & 1) * 8 + (l & 7);
    const int kb = t4 >> 1;
    const uint32_t pa = (uint32_t)(m_off + r8) * 256u;
    const uint32_t pb = (uint32_t)(n_off + r8) * 256u;
    const int l7 = l & 7;

    // ---- W -> fp16 SMEM (stage0, temporary), then ldsm all fragments into regs ----
    {
        const float4* Wp = reinterpret_cast<const float4*>(W);
#pragma unroll
        for (int i = 0; i < 16; ++i)
            convert_row(Wp[(w * 16 + i) * 32 + l], base, w * 16 + i, l);
    }
    __syncthreads();

    uint32_t wb[64];                 // B fragments: 8 ks x 8 regs
#pragma unroll
    for (int ks = 0; ks < 8; ++ks) {
        uint32_t cs = ((uint32_t)((2 * ks + kb) ^ l7)) << 4;
        ldsm4(base + pb + cs,        wb + ks * 8);
        ldsm4(base + pb + 4096 + cs, wb + ks * 8 + 4);
    }
    __syncthreads();                 // stage0 free for x

    // bias for this thread's 8 output columns
    float2 bj[4];
#pragma unroll
    for (int j = 0; j < 4; ++j) {
        int col = n_off + j * 8 + (l & 3) * 2;
        bj[j].x = __ldg(bias + col);
        bj[j].y = __ldg(bias + col + 1);
    }

    const float4* x4 = reinterpret_cast<const float4*>(x);
    const int stride = gridDim.x;
    int tile = blockIdx.x;
    int tn   = tile + stride;

    // Prologue: tile -> regs -> stage0; tn -> regs.
    float4 xr[16];
    if (tile < N_TILES) {
        const float4* src = x4 + (size_t)tile * 4096;
#pragma unroll
        for (int i = 0; i < 16; ++i) xr[i] = __ldcs(&src[(w * 16 + i) * 32 + l]);
#pragma unroll
        for (int i = 0; i < 16; ++i) convert_row(xr[i], base, w * 16 + i, l);
    }
    if (tn < N_TILES) {
        const float4* src = x4 + (size_t)tn * 4096;
#pragma unroll
        for (int i = 0; i < 16; ++i) xr[i] = __ldcs(&src[(w * 16 + i) * 32 + l]);
    }
    __syncthreads();

    uint32_t bufoff = 0;
    while (tile < N_TILES) {
        const int t2 = tn + stride;
        const int t3 = t2 + stride;
        const bool cvt = (tn < N_TILES);
        const bool pre = (t2 < N_TILES);
        const uint32_t cur = base + bufoff;
        const uint32_t nxt = base + (bufoff ^ XSTAGE_BYTES);
        const float4* src2 = x4 + (size_t)t2 * 4096;

        // ---- prefetch tile t3 into L2: dependency-free burst, drives DRAM ----
        // Warp's slice = 16 rows x 128B; 4 lanes x 16 lines cover it exactly.
        if (t3 < N_TILES && l < 4) {
            const float4* src3 = x4 + (size_t)t3 * 4096;
#pragma unroll
            for (int i = 0; i < 16; ++i)
                prefetch_l2(&src3[(w * 16 + i) * 32 + l * 8]);
        }

        // accum init = bias (epilogue add folded in)
        float c[64];
#pragma unroll
        for (int mi = 0; mi < 4; ++mi)
#pragma unroll
            for (int j = 0; j < 4; ++j) {
                float* cc = c + (mi * 4 + j) * 4;
                cc[0] = bj[j].x; cc[1] = bj[j].y;
                cc[2] = bj[j].x; cc[3] = bj[j].y;
            }

        // Fused mainloop.
        //   ks 0-3: 4 ldsm.x4 + [4 convert rows + 4 LDG.128 (L2 hits)] + 16 HMMA
        //   ks 4-7: pure ldsm + HMMA drain
#pragma unroll
        for (int ks = 0; ks < 8; ++ks) {
            uint32_t cs = ((uint32_t)((2 * ks + kb) ^ l7)) << 4;
            uint32_t a[16];
            ldsm4(cur + pa + cs,         a + 0);
            ldsm4(cur + pa + 4096 + cs,  a + 4);
            ldsm4(cur + pa + 8192 + cs,  a + 8);
            ldsm4(cur + pa + 12288 + cs, a + 12);

            if (ks < 4) {
#pragma unroll
                for (int q = 0; q < 4; ++q) {
                    int i = ks * 4 + q;
                    if (cvt) convert_row(xr[i], nxt, w * 16 + i, l);
                    if (pre) xr[i] = __ldcs(&src2[(w * 16 + i) * 32 + l]);
                }
            }

            const uint32_t* b = wb + ks * 8;
#pragma unroll
            for (int mi = 0; mi < 4; ++mi)
#pragma unroll
                for (int j = 0; j < 4; ++j) {
                    float* cc = c + (mi * 4 + j) * 4;
                    int bi = (j >> 1) * 4 + (j & 1);
                    mma_fp16(cc, a + mi * 4, b[bi], b[bi + 2]);
                }
        }

        // ---- epilogue: streaming store ----
        {
            float* ob = out + (size_t)tile * 128 * 128;
#pragma unroll
            for (int mi = 0; mi < 4; ++mi)
#pragma unroll
                for (int j = 0; j < 4; ++j) {
                    int ci = (mi * 4 + j) * 4;
                    int r  = m_off + mi * 16 + (l >> 2);
                    int col = n_off + j * 8 + (l & 3) * 2;
                    float2 v0 = { c[ci + 0], c[ci + 1] };
                    float2 v1 = { c[ci + 2], c[ci + 3] };
                    float* po = ob + (size_t)r * 128 + col;
                    __stcs(reinterpret_cast<float2*>(po), v0);
                    __stcs(reinterpret_cast<float2*>(po + 8 * 128), v1);
                }
        }

        __syncthreads();   // stage swap
        tile = tn;
        tn = t2;
        bufoff ^= XSTAGE_BYTES;
    }
}

extern "C" void kernel_launch(void* const* d_in, const int* in_sizes, int n_in,
                              void* d_out, int out_size) {
    const float* x = (const float*)d_in[0];
    const float* W = (const float*)d_in[1];
    const float* b = (const float*)d_in[2];
    float* out = (float*)d_out;

    int nsm = 148;
    cudaDeviceGetAttribute(&nsm, cudaDevAttrMultiProcessorCount, 0);

    cudaFuncSetAttribute(linear_mma_kernel,
                         cudaFuncAttributeMaxDynamicSharedMemorySize, SMEM_BYTES);
    linear_mma_kernel<<<nsm, THREADS, SMEM_BYTES>>>(x, W, b, out);
}

// round 13
// speedup vs baseline: 1.5276x; 1.5276x over previous
#include <cuda_runtime.h>
#include <cuda_fp16.h>
#include <cstdint>

// Problem: out[524288,128] = x[524288,128] @ W[128,128]^T + b[128]
// Single fp16 GEMM (fp32 accumulate). W fragments in registers.
// R10 + (a) LDGs shifted one ks after converts (WAR pre-resolved),
//      (b) split arrive/sync barrier so epilogue overlaps tail MMA.
#define BATCH    524288
#define N_TILES  4096            // BATCH / 128
#define THREADS  256             // 8 warps: 2(M) x 4(N) grid of 64x32 warp tiles

// SMEM: two X stages (fp16 128x128, XOR-swizzled 16B chunks), 32KB each.
#define XSTAGE_BYTES 32768
#define SMEM_BYTES   (65536 + 1024)

__device__ __forceinline__ uint32_t smem_u32(const void* p) {
    uint32_t a;
    asm("{ .reg .u64 t; cvta.to.shared.u64 t, %1; cvt.u32.u64 %0, t; }" : "=r"(a) : "l"(p));
    return a;
}

__device__ __forceinline__ uint32_t pack_f16x2(float a, float b) {
    uint32_t r;
    asm("cvt.rn.f16x2.f32 %0, %1, %2;" : "=r"(r) : "f"(b), "f"(a));  // lo=a, hi=b
    return r;
}

__device__ __forceinline__ void ldsm4(uint32_t addr, uint32_t* r) {
    asm volatile("ldmatrix.sync.aligned.m8n8.x4.shared.b16 {%0,%1,%2,%3}, [%4];"
                 : "=r"(r[0]), "=r"(r[1]), "=r"(r[2]), "=r"(r[3]) : "r"(addr));
}

__device__ __forceinline__ void mma_fp16(float* c, const uint32_t* a, uint32_t b0, uint32_t b1) {
    asm volatile("mma.sync.aligned.m16n8k16.row.col.f32.f16.f16.f32 "
                 "{%0,%1,%2,%3}, {%4,%5,%6,%7}, {%8,%9}, {%0,%1,%2,%3};"
                 : "+f"(c[0]), "+f"(c[1]), "+f"(c[2]), "+f"(c[3])
                 : "r"(a[0]), "r"(a[1]), "r"(a[2]), "r"(a[3]), "r"(b0), "r"(b1));
}

// Store one fp32x4 row chunk (row, k=4l..4l+3) into swizzled fp16 SMEM.
// Element (row,k): row*256 + (((k>>3) ^ (row&7))<<4) + (k&7)*2
__device__ __forceinline__ void convert_row(float4 v, uint32_t dst, int row, int l) {
    uint32_t off = (uint32_t)row * 256u
                 + (((uint32_t)(l >> 1) ^ (uint32_t)(row & 7)) << 4)
                 + (uint32_t)((l & 1) * 8);
    uint32_t p0 = pack_f16x2(v.x, v.y);
    uint32_t p1 = pack_f16x2(v.z, v.w);
    asm volatile("st.shared.v2.b32 [%0], {%1,%2};" :: "r"(dst + off), "r"(p0), "r"(p1) : "memory");
}

__global__ void __launch_bounds__(THREADS, 1)
linear_mma_kernel(const float* __restrict__ x,
                  const float* __restrict__ W,
                  const float* __restrict__ bias,
                  float* __restrict__ out) {
    extern __shared__ char smem_raw[];
    uint32_t base = (smem_u32(smem_raw) + 1023u) & ~1023u;

    const int tid = threadIdx.x;
    const int w   = tid >> 5;        // warp 0..7
    const int l   = tid & 31;

    // Warp tile: 64(M) x 32(N).  2x4 warp grid.
    const int m_off = (w >> 2) * 64;
    const int n_off = (w & 3) * 32;

    // ldmatrix lane mapping (x4 over 16x16 fp16 tiles)
    const int t4 = l >> 3;
    const int r8 = (t4 & 1) * 8 + (l & 7);
    const int kb = t4 >> 1;
    const uint32_t pa = (uint32_t)(m_off + r8) * 256u;
    const uint32_t pb = (uint32_t)(n_off + r8) * 256u;
    const int l7 = l & 7;

    // ---- W -> fp16 SMEM (stage0, temporary), then ldsm all fragments into regs ----
    {
        const float4* Wp = reinterpret_cast<const float4*>(W);
#pragma unroll
        for (int i = 0; i < 16; ++i)
            convert_row(Wp[(w * 16 + i) * 32 + l], base, w * 16 + i, l);
    }
    __syncthreads();

    uint32_t wb[64];                 // B fragments: 8 ks x 8 regs
#pragma unroll
    for (int ks = 0; ks < 8; ++ks) {
        uint32_t cs = ((uint32_t)((2 * ks + kb) ^ l7)) << 4;
        ldsm4(base + pb + cs,        wb + ks * 8);
        ldsm4(base + pb + 4096 + cs, wb + ks * 8 + 4);
    }
    __syncthreads();                 // stage0 free for x

    // bias for this thread's 8 output columns
    float2 bj[4];
#pragma unroll
    for (int j = 0; j < 4; ++j) {
        int col = n_off + j * 8 + (l & 3) * 2;
        bj[j].x = __ldg(bias + col);
        bj[j].y = __ldg(bias + col + 1);
    }

    const float4* x4 = reinterpret_cast<const float4*>(x);
    const int stride = gridDim.x;
    int tile = blockIdx.x;
    int tn   = tile + stride;

    // Prologue: tile -> regs -> stage0; tn -> regs.
    float4 xr[16];
    if (tile < N_TILES) {
        const float4* src = x4 + (size_t)tile * 4096;
#pragma unroll
        for (int i = 0; i < 16; ++i) xr[i] = __ldcs(&src[(w * 16 + i) * 32 + l]);
#pragma unroll
        for (int i = 0; i < 16; ++i) convert_row(xr[i], base, w * 16 + i, l);
    }
    if (tn < N_TILES) {
        const float4* src = x4 + (size_t)tn * 4096;
#pragma unroll
        for (int i = 0; i < 16; ++i) xr[i] = __ldcs(&src[(w * 16 + i) * 32 + l]);
    }
    __syncthreads();

    uint32_t bufoff = 0;
    while (tile < N_TILES) {
        const int t2 = tn + stride;
        const bool cvt = (tn < N_TILES);
        const bool pre = (t2 < N_TILES);
        const uint32_t cur = base + bufoff;
        const uint32_t nxt = base + (bufoff ^ XSTAGE_BYTES);
        const float4* src2 = x4 + (size_t)t2 * 4096;

        // accum init = bias (epilogue add folded in)
        float c[64];
#pragma unroll
        for (int mi = 0; mi < 4; ++mi)
#pragma unroll
            for (int j = 0; j < 4; ++j) {
                float* cc = c + (mi * 4 + j) * 4;
                cc[0] = bj[j].x; cc[1] = bj[j].y;
                cc[2] = bj[j].x; cc[3] = bj[j].y;
            }

        // Fused mainloop.
        //   converts: 4 rows/ks in ks0-3 (rows 4ks..4ks+3 -> nxt stage)
        //   LDGs:     4 rows/ks in ks1-4 (rows 4(ks-1)..), i.e. one ks AFTER the
        //             convert that frees each xr slot -> WAR already resolved,
        //             ptxas can hoist LDGs to the top of the ks block.
#pragma unroll
        for (int ks = 0; ks < 8; ++ks) {
            uint32_t cs = ((uint32_t)((2 * ks + kb) ^ l7)) << 4;
            uint32_t a[16];
            ldsm4(cur + pa + cs,         a + 0);
            ldsm4(cur + pa + 4096 + cs,  a + 4);
            ldsm4(cur + pa + 8192 + cs,  a + 8);
            ldsm4(cur + pa + 12288 + cs, a + 12);

            if (ks >= 1 && ks < 5 && pre) {
#pragma unroll
                for (int q = 0; q < 4; ++q) {
                    int i = (ks - 1) * 4 + q;
                    xr[i] = __ldcs(&src2[(w * 16 + i) * 32 + l]);
                }
            }
            if (ks < 4 && cvt) {
#pragma unroll
                for (int q = 0; q < 4; ++q) {
                    int i = ks * 4 + q;
                    convert_row(xr[i], nxt, w * 16 + i, l);
                }
            }

            const uint32_t* b = wb + ks * 8;
#pragma unroll
            for (int mi = 0; mi < 4; ++mi)
#pragma unroll
                for (int j = 0; j < 4; ++j) {
                    float* cc = c + (mi * 4 + j) * 4;
                    int bi = (j >> 1) * 4 + (j & 1);
                    mma_fp16(cc, a + mi * 4, b[bi], b[bi + 2]);
                }
        }

        // Split barrier: arrive now (all smem reads/writes for this stage are
        // issued), overlap epilogue with other warps' tail MMA, sync after.
        asm volatile("bar.arrive 0, %0;" :: "r"(2 * THREADS) : "memory");

        // ---- epilogue: streaming store ----
        {
            float* ob = out + (size_t)tile * 128 * 128;
#pragma unroll
            for (int mi = 0; mi < 4; ++mi)
#pragma unroll
                for (int j = 0; j < 4; ++j) {
                    int ci = (mi * 4 + j) * 4;
                    int r  = m_off + mi * 16 + (l >> 2);
                    int col = n_off + j * 8 + (l & 3) * 2;
                    float2 v0 = { c[ci + 0], c[ci + 1] };
                    float2 v1 = { c[ci + 2], c[ci + 3] };
                    float* po = ob + (size_t)r * 128 + col;
                    __stcs(reinterpret_cast<float2*>(po), v0);
                    __stcs(reinterpret_cast<float2*>(po + 8 * 128), v1);
                }
        }

        asm volatile("bar.sync 0, %0;" :: "r"(2 * THREADS) : "memory");
        tile = tn;
        tn = t2;
        bufoff ^= XSTAGE_BYTES;
    }
}

extern "C" void kernel_launch(void* const* d_in, const int* in_sizes, int n_in,
                              void* d_out, int out_size) {
    const float* x = (const float*)d_in[0];
    const float* W = (const float*)d_in[1];
    const float* b = (const float*)d_in[2];
    float* out = (float*)d_out;

    int nsm = 148;
    cudaDeviceGetAttribute(&nsm, cudaDevAttrMultiProcessorCount, 0);

    cudaFuncSetAttribute(linear_mma_kernel,
                         cudaFuncAttributeMaxDynamicSharedMemorySize, SMEM_BYTES);
    linear_mma_kernel<<<nsm, THREADS, SMEM_BYTES>>>(x, W, b, out);
}